// round 11
// baseline (speedup 1.0000x reference)
#include <cuda_runtime.h>
#include <cstdint>

#define B_BAGS 16384
#define GRID_BLOCKS 8192

// Per-table exclusive prefix offsets (scratch, computed each launch).
__device__ int g_off[4][B_BAGS + 1];
__device__ int g_flag;   // scan-done counter (0..4), self-resets each launch
__device__ int g_done;   // block-done counter, self-resets each launch

// ---------------------------------------------------------------------------
// Fused kernel: blocks 0-3 scan their table's lens into g_off, publish via
// flag; all other blocks spin until flag==4, then pool. Table-interleaved
// mapping (table = blockIdx & 3) so every resident wave mixes DRAM-heavy
// tables (0/3) with L2-resident tables (1/2). Default cache policy on all
// gather loads (catches dim-64 repeat draws AND W1/W2 reuse); output
// streamed with __stcs. Output: [B, 288], column bases {0, 64, 192, 224}.
// ---------------------------------------------------------------------------
__global__ __launch_bounds__(256)
void fused_pool_kernel(const float* __restrict__ W0, const float* __restrict__ W1,
                       const float* __restrict__ W2, const float* __restrict__ W3,
                       const int* __restrict__ ids0, const int* __restrict__ ids1,
                       const int* __restrict__ ids2, const int* __restrict__ ids3,
                       const int* __restrict__ l0, const int* __restrict__ l1,
                       const int* __restrict__ l2, const int* __restrict__ l3,
                       float* __restrict__ out) {
    int tid   = threadIdx.x;
    int lane  = tid & 31;
    int wid   = tid >> 5;
    int table = blockIdx.x & 3;

    if (blockIdx.x < 4) {
        // ---- scan: 256 threads, 64 lens each (as 16x int4) ----
        const int* lens = (table == 0) ? l0 : (table == 1) ? l1
                        : (table == 2) ? l2 : l3;
        int* off = g_off[table];
        const int4* l4 = (const int4*)lens + tid * 16;

        int sum = 0;
#pragma unroll
        for (int k = 0; k < 16; k++) {
            int4 v = l4[k];
            sum += (v.x + v.y) + (v.z + v.w);
        }
        // block scan of 256 thread sums (8 warps)
        __shared__ int wsum[8];
        int incl = sum;
#pragma unroll
        for (int d = 1; d < 32; d <<= 1) {
            int x = __shfl_up_sync(0xffffffffu, incl, d);
            if (lane >= d) incl += x;
        }
        if (lane == 31) wsum[wid] = incl;
        __syncthreads();
        if (wid == 0 && lane < 8) {
            int w = wsum[lane];
            int wincl = w;
#pragma unroll
            for (int d = 1; d < 8; d <<= 1) {
                int x = __shfl_up_sync(0x000000ffu, wincl, d);
                if (lane >= d) wincl += x;
            }
            wsum[lane] = wincl - w;   // exclusive base per warp
        }
        __syncthreads();
        int run = wsum[wid] + (incl - sum);   // exclusive prefix for this chunk
#pragma unroll
        for (int k = 0; k < 16; k++) {
            int4 v = l4[k];
            int b = tid * 64 + k * 4;
            off[b + 0] = run; run += v.x;
            off[b + 1] = run; run += v.y;
            off[b + 2] = run; run += v.z;
            off[b + 3] = run; run += v.w;
        }
        if (tid == 255) off[B_BAGS] = run;
        __threadfence();          // each thread publishes its own off[] writes
        __syncthreads();          // all fences done before flag
        if (tid == 0) atomicAdd(&g_flag, 1);
        // scan block only needs its OWN table's offsets -> proceed to pool
    } else {
        if (tid == 0) {
            while (*(volatile int*)&g_flag < 4) __nanosleep(32);
        }
        __syncthreads();
        __threadfence();          // acquire: order g_off reads after flag
    }

    // ---- pooling: warp per bag, 8 warps/block ----
    int bag = ((blockIdx.x >> 2) << 3) + wid;
    const int* off = g_off[table];
    int s = off[bag];
    int e = off[bag + 1];
    float* o = out + (size_t)bag * 288;

    if (table == 0 || table == 3) {
        // dim 64: float2 per lane (256B/row), default cache (catch repeats).
        const float* W   = (table == 0) ? W0 : W3;
        const int*   ids = (table == 0) ? ids0 : ids3;
        int cb = (table == 0) ? 0 : 224;
        float2 acc = make_float2(0.f, 0.f);
        int j = s;
        for (; j + 8 <= e; j += 8) {
            int idx[8];
#pragma unroll
            for (int k = 0; k < 8; k++) idx[k] = ids[j + k];
            float2 v[8];
#pragma unroll
            for (int k = 0; k < 8; k++)
                v[k] = *((const float2*)(W + (size_t)idx[k] * 64) + lane);
#pragma unroll
            for (int k = 0; k < 8; k++) { acc.x += v[k].x; acc.y += v[k].y; }
        }
        for (; j < e; j++) {
            float2 a = *((const float2*)(W + (size_t)ids[j] * 64) + lane);
            acc.x += a.x; acc.y += a.y;
        }
        __stcs((float2*)(o + cb) + lane, acc);
    } else if (table == 1) {
        // dim 128: float4 per lane (512B/row). W1 = 51MB, L2-resident.
        float4 acc = make_float4(0.f, 0.f, 0.f, 0.f);
        int j = s;
        for (; j + 8 <= e; j += 8) {
            int idx[8];
#pragma unroll
            for (int k = 0; k < 8; k++) idx[k] = ids1[j + k];
            float4 v[8];
#pragma unroll
            for (int k = 0; k < 8; k++)
                v[k] = *((const float4*)(W1 + (size_t)idx[k] * 128) + lane);
#pragma unroll
            for (int k = 0; k < 8; k++) {
                acc.x += v[k].x; acc.y += v[k].y; acc.z += v[k].z; acc.w += v[k].w;
            }
        }
        for (; j < e; j++) {
            float4 a = *((const float4*)(W1 + (size_t)ids1[j] * 128) + lane);
            acc.x += a.x; acc.y += a.y; acc.z += a.z; acc.w += a.w;
        }
        __stcs((float4*)(o + 64) + lane, acc);
    } else {
        // dim 32: 1 float per lane (128B/row). W2 = 64MB, L2-resident.
        float acc = 0.f;
        int j = s;
        for (; j + 8 <= e; j += 8) {
            int idx[8];
#pragma unroll
            for (int k = 0; k < 8; k++) idx[k] = ids2[j + k];
            float v[8];
#pragma unroll
            for (int k = 0; k < 8; k++) v[k] = W2[(size_t)idx[k] * 32 + lane];
#pragma unroll
            for (int k = 0; k < 8; k++) acc += v[k];
        }
        for (; j < e; j++) acc += W2[(size_t)ids2[j] * 32 + lane];
        __stcs(o + 192 + lane, acc);
    }

    // ---- epilogue: last block resets flag/done for next graph replay ----
    __syncthreads();
    if (tid == 0) {
        __threadfence();
        if (atomicAdd(&g_done, 1) == GRID_BLOCKS - 1) {
            g_flag = 0;
            g_done = 0;
        }
    }
}

// ---------------------------------------------------------------------------
// kernel_launch: identify inputs by element count (order-robust), one launch.
// ---------------------------------------------------------------------------
extern "C" void kernel_launch(void* const* d_in, const int* in_sizes, int n_in,
                              void* d_out, int out_size) {
    const float *W0 = nullptr, *W1 = nullptr, *W2 = nullptr, *W3 = nullptr;
    const int *ids0 = nullptr, *ids1 = nullptr, *ids2 = nullptr, *ids3 = nullptr;
    const int *lens[4] = {nullptr, nullptr, nullptr, nullptr};
    int nlens = 0;
    bool seenW64 = false, seenIds819 = false;

    for (int i = 0; i < n_in; i++) {
        long long sz = in_sizes[i];
        void* p = d_in[i];
        if (sz == 64000000LL) {               // 1M x 64 (tables 0 and 3)
            if (!seenW64) { W0 = (const float*)p; seenW64 = true; }
            else          { W3 = (const float*)p; }
        } else if (sz == 12800000LL) {        // 100K x 128
            W1 = (const float*)p;
        } else if (sz == 16000000LL) {        // 500K x 32
            W2 = (const float*)p;
        } else if (sz == 819200LL) {          // ids for tables 0 and 3
            if (!seenIds819) { ids0 = (const int*)p; seenIds819 = true; }
            else             { ids3 = (const int*)p; }
        } else if (sz == 327680LL) {
            ids1 = (const int*)p;
        } else if (sz == 1638400LL) {
            ids2 = (const int*)p;
        } else if (sz == 16384LL) {
            if (nlens < 4) lens[nlens++] = (const int*)p;
        }
    }

    fused_pool_kernel<<<GRID_BLOCKS, 256>>>(W0, W1, W2, W3,
                                            ids0, ids1, ids2, ids3,
                                            lens[0], lens[1], lens[2], lens[3],
                                            (float*)d_out);
}

// round 12
// speedup vs baseline: 1.3955x; 1.3955x over previous
#include <cuda_runtime.h>
#include <cstdint>

#define B_BAGS 16384

// Per-table exclusive prefix offsets (scratch, computed each launch).
__device__ int g_off[4][B_BAGS + 1];

// ---------------------------------------------------------------------------
// Scan kernel: one block per table, 1024 threads, 16 lens each, shfl-scan.
// ---------------------------------------------------------------------------
__global__ void scan_kernel(const int* __restrict__ l0, const int* __restrict__ l1,
                            const int* __restrict__ l2, const int* __restrict__ l3) {
    const int* lens = (blockIdx.x == 0) ? l0 : (blockIdx.x == 1) ? l1
                    : (blockIdx.x == 2) ? l2 : l3;
    int* off = g_off[blockIdx.x];
    __shared__ int warp_sums[32];

    int t    = threadIdx.x;
    int wid  = t >> 5;
    int lane = t & 31;

    int4 v0 = ((const int4*)lens)[t * 4 + 0];
    int4 v1 = ((const int4*)lens)[t * 4 + 1];
    int4 v2 = ((const int4*)lens)[t * 4 + 2];
    int4 v3 = ((const int4*)lens)[t * 4 + 3];
    int vals[16] = {v0.x, v0.y, v0.z, v0.w, v1.x, v1.y, v1.z, v1.w,
                    v2.x, v2.y, v2.z, v2.w, v3.x, v3.y, v3.z, v3.w};

    int s = 0;
    int pre[16];
#pragma unroll
    for (int k = 0; k < 16; k++) { pre[k] = s; s += vals[k]; }

    int incl = s;
#pragma unroll
    for (int d = 1; d < 32; d <<= 1) {
        int x = __shfl_up_sync(0xffffffffu, incl, d);
        if (lane >= d) incl += x;
    }
    if (lane == 31) warp_sums[wid] = incl;
    __syncthreads();

    if (wid == 0) {
        int w = warp_sums[lane];
        int wincl = w;
#pragma unroll
        for (int d = 1; d < 32; d <<= 1) {
            int x = __shfl_up_sync(0xffffffffu, wincl, d);
            if (lane >= d) wincl += x;
        }
        warp_sums[lane] = wincl - w;
    }
    __syncthreads();

    int base = warp_sums[wid] + (incl - s);
#pragma unroll
    for (int k = 0; k < 16; k++) off[t * 16 + k] = base + pre[k];
    if (t == 1023) off[B_BAGS] = base + s;
}

// ---------------------------------------------------------------------------
// Pooling kernel: warp per (bag, table), 8 warps/block.
// Table-INTERLEAVED grid (table = blockIdx & 3): every resident wave mixes
// DRAM-heavy tables (0/3) with L2-resident tables (1/2) -> overlapped DRAM
// and L2 service (measured: DRAM 61.8% -> 71.5%).
// DEFAULT cache policy on all gather loads: catches the ~260K repeat draws
// per dim-64 table (~117MB of L2 hits that __ldcs threw away in R10) and
// preserves W1/W2 residency. __stcs only on the output (never re-read).
// Output layout: [B, 288], column bases {0, 64, 192, 224}.
// ---------------------------------------------------------------------------
__global__ __launch_bounds__(256)
void pool_kernel(const float* __restrict__ W0, const float* __restrict__ W1,
                 const float* __restrict__ W2, const float* __restrict__ W3,
                 const int* __restrict__ ids0, const int* __restrict__ ids1,
                 const int* __restrict__ ids2, const int* __restrict__ ids3,
                 float* __restrict__ out) {
    int table = blockIdx.x & 3;                               // interleaved
    int bag   = ((blockIdx.x >> 2) << 3) + (threadIdx.x >> 5);
    int lane  = threadIdx.x & 31;

    const int* off = g_off[table];
    int s = off[bag];
    int e = off[bag + 1];
    float* o = out + (size_t)bag * 288;

    if (table == 0 || table == 3) {
        // dim 64: float2 per lane (256B/row), default cache.
        const float* W   = (table == 0) ? W0 : W3;
        const int*   ids = (table == 0) ? ids0 : ids3;
        int cb = (table == 0) ? 0 : 224;
        float2 acc = make_float2(0.f, 0.f);
        int j = s;
        for (; j + 8 <= e; j += 8) {
            int idx[8];
#pragma unroll
            for (int k = 0; k < 8; k++) idx[k] = ids[j + k];
            float2 v[8];
#pragma unroll
            for (int k = 0; k < 8; k++)
                v[k] = *((const float2*)(W + (size_t)idx[k] * 64) + lane);
#pragma unroll
            for (int k = 0; k < 8; k++) { acc.x += v[k].x; acc.y += v[k].y; }
        }
        for (; j < e; j++) {
            float2 a = *((const float2*)(W + (size_t)ids[j] * 64) + lane);
            acc.x += a.x; acc.y += a.y;
        }
        __stcs((float2*)(o + cb) + lane, acc);
    } else if (table == 1) {
        // dim 128: float4 per lane (512B/row). W1 = 51MB, L2-resident.
        float4 acc = make_float4(0.f, 0.f, 0.f, 0.f);
        int j = s;
        for (; j + 8 <= e; j += 8) {
            int idx[8];
#pragma unroll
            for (int k = 0; k < 8; k++) idx[k] = ids1[j + k];
            float4 v[8];
#pragma unroll
            for (int k = 0; k < 8; k++)
                v[k] = *((const float4*)(W1 + (size_t)idx[k] * 128) + lane);
#pragma unroll
            for (int k = 0; k < 8; k++) {
                acc.x += v[k].x; acc.y += v[k].y; acc.z += v[k].z; acc.w += v[k].w;
            }
        }
        for (; j < e; j++) {
            float4 a = *((const float4*)(W1 + (size_t)ids1[j] * 128) + lane);
            acc.x += a.x; acc.y += a.y; acc.z += a.z; acc.w += a.w;
        }
        __stcs((float4*)(o + 64) + lane, acc);
    } else {
        // dim 32: 1 float per lane (128B/row). W2 = 64MB, L2-resident.
        float acc = 0.f;
        int j = s;
        for (; j + 8 <= e; j += 8) {
            int idx[8];
#pragma unroll
            for (int k = 0; k < 8; k++) idx[k] = ids2[j + k];
            float v[8];
#pragma unroll
            for (int k = 0; k < 8; k++) v[k] = W2[(size_t)idx[k] * 32 + lane];
#pragma unroll
            for (int k = 0; k < 8; k++) acc += v[k];
        }
        for (; j < e; j++) acc += W2[(size_t)ids2[j] * 32 + lane];
        __stcs(o + 192 + lane, acc);
    }
}

// ---------------------------------------------------------------------------
// kernel_launch: identify inputs by element count (order-robust), then launch.
// ---------------------------------------------------------------------------
extern "C" void kernel_launch(void* const* d_in, const int* in_sizes, int n_in,
                              void* d_out, int out_size) {
    const float *W0 = nullptr, *W1 = nullptr, *W2 = nullptr, *W3 = nullptr;
    const int *ids0 = nullptr, *ids1 = nullptr, *ids2 = nullptr, *ids3 = nullptr;
    const int *lens[4] = {nullptr, nullptr, nullptr, nullptr};
    int nlens = 0;
    bool seenW64 = false, seenIds819 = false;

    for (int i = 0; i < n_in; i++) {
        long long sz = in_sizes[i];
        void* p = d_in[i];
        if (sz == 64000000LL) {               // 1M x 64 (tables 0 and 3)
            if (!seenW64) { W0 = (const float*)p; seenW64 = true; }
            else          { W3 = (const float*)p; }
        } else if (sz == 12800000LL) {        // 100K x 128
            W1 = (const float*)p;
        } else if (sz == 16000000LL) {        // 500K x 32
            W2 = (const float*)p;
        } else if (sz == 819200LL) {          // ids for tables 0 and 3
            if (!seenIds819) { ids0 = (const int*)p; seenIds819 = true; }
            else             { ids3 = (const int*)p; }
        } else if (sz == 327680LL) {
            ids1 = (const int*)p;
        } else if (sz == 1638400LL) {
            ids2 = (const int*)p;
        } else if (sz == 16384LL) {
            if (nlens < 4) lens[nlens++] = (const int*)p;
        }
    }

    scan_kernel<<<4, 1024>>>(lens[0], lens[1], lens[2], lens[3]);
    pool_kernel<<<B_BAGS / 2, 256>>>(W0, W1, W2, W3,
                                     ids0, ids1, ids2, ids3,
                                     (float*)d_out);
}